// round 9
// baseline (speedup 1.0000x reference)
#include <cuda_runtime.h>

#define NB   32        // batch
#define NE   200000    // entities
#define NT   1000000   // triples
#define NR   256       // relations
#define DQ   768       // question dim
#define DIN  1280      // DQ + 2*NR
#define NEB  (NE * NB) // 6.4M floats
#define NJ   257       // 256 W_inf rows + 1 W_att row

// ---- device scratch (static; no allocation) ----
__device__ float g_x0T[NEB];           // transposed seed x: [e][b] (active rows)
__device__ float g_xh[3 * NEB];        // hop outputs, entity-major
__device__ float g_rT[3 * NR * NB];    // r per hop: [j][b]
__device__ float g_c[3 * NB];          // attention logits per hop
__device__ unsigned g_lm[4 * NE];      // per-entity 32-bit lane-activity mask per hop

// ---- transpose x (B x NE) -> (NE x B), sparse writes + hop-0 lane mask ----
__global__ void k_transpose_x(const float* __restrict__ src) {
    __shared__ float s[32][33];
    int lane = threadIdx.x, ty = threadIdx.y;
    int cbase = blockIdx.x * 32;
#pragma unroll
    for (int row = ty; row < 32; row += 8)              // row = b
        s[row][lane] = src[(size_t)row * NE + cbase + lane];
    __syncthreads();
#pragma unroll
    for (int row = ty; row < 32; row += 8) {            // row = entity offset
        float v = s[lane][row];                         // lane = b
        unsigned b = __ballot_sync(0xffffffffu, v != 0.0f);
        if (b) g_x0T[(size_t)(cbase + row) * NB + lane] = v;  // active rows only
        if (lane == 0) g_lm[cbase + row] = b;           // exact hop-0 lane mask
    }
}

// ---- zero lane masks for hops 1..3 ----
__global__ void k_zero_lm() {
    int i = blockIdx.x * blockDim.x + threadIdx.x;
    if (i < 3 * NE) g_lm[NE + i] = 0u;
}

// ---- reachability: lm[hop+1][obj] |= lm[hop][subj] ----
__global__ void k_reach(const int* __restrict__ subj,
                        const int* __restrict__ obj, int hop) {
    int t = blockIdx.x * blockDim.x + threadIdx.x;
    if (t < NT) {
        unsigned lm = g_lm[hop * NE + subj[t]];
        if (lm) atomicOr(&g_lm[(hop + 1) * NE + obj[t]], lm);
    }
}

// ---- zero only rows of hop output that can be written (lm[hop+1] != 0) ----
__global__ void k_zero_masked(int hop) {
    int i = blockIdx.x * blockDim.x + threadIdx.x;     // over NE*8 quads
    int e = i >> 3, q = i & 7;
    if (e < NE && g_lm[(hop + 1) * NE + e])
        reinterpret_cast<float4*>(g_xh + (size_t)hop * NEB + (size_t)e * NB)[q] =
            make_float4(0.f, 0.f, 0.f, 0.f);
}

// ---- zero gemm accumulators ----
__global__ void k_zero_small() {
    int i = blockIdx.x * blockDim.x + threadIdx.x;
    if (i < 3 * NR * NB) g_rT[i] = 0.f;
    if (i < 3 * NB) g_c[i] = 0.f;
}

// ---- r_0 / c_0 = h_q @ [W_inf; W_att][:, :768].T  (split-d, atomic accum)
__global__ void k_gemm_base(const float* __restrict__ W_inf,
                            const float* __restrict__ W_att,
                            const float* __restrict__ h_q) {
    __shared__ float sh[192][33];
    __shared__ float sr[8][32];
    int lane = threadIdx.x, ty = threadIdx.y;
    int tid = ty * 32 + lane;
    int j = blockIdx.x;
    int d0 = blockIdx.y * 192;
#pragma unroll
    for (int k = 0; k < 24; k++) {                      // 6144 elems, coalesced
        int idx = tid + k * 256;
        int b = idx / 192, d = idx % 192;
        sh[d][b] = h_q[(size_t)b * DQ + d0 + d];
    }
    __syncthreads();
    const float* w = (j == 256) ? W_att : W_inf + (size_t)j * DIN;
    int dd = ty * 24;
    float a0 = 0.f, a1 = 0.f, a2 = 0.f, a3 = 0.f;
#pragma unroll
    for (int d = dd; d < dd + 24; d += 4) {
        a0 += sh[d + 0][lane] * w[d0 + d + 0];
        a1 += sh[d + 1][lane] * w[d0 + d + 1];
        a2 += sh[d + 2][lane] * w[d0 + d + 2];
        a3 += sh[d + 3][lane] * w[d0 + d + 3];
    }
    sr[ty][lane] = (a0 + a1) + (a2 + a3);
    __syncthreads();
    if (ty == 0) {
        float t = 0.f;
#pragma unroll
        for (int k = 0; k < 8; k++) t += sr[k][lane];
        if (j == 256) atomicAdd(&g_c[lane], t);
        else          atomicAdd(&g_rT[j * NB + lane], t);
    }
}

// ---- hop 1/2 increment, split-k: out = hop0_out + r_parts @ W[:, 768:].T ----
__global__ void k_gemm_hop(const float* __restrict__ W_inf,
                           const float* __restrict__ W_att, int hop) {
    int lane = threadIdx.x, ty = threadIdx.y;
    int j = blockIdx.x;
    const float* w = (j == 256) ? W_att : W_inf + (size_t)j * DIN;
    int kk0 = blockIdx.y * 128 + ty * 16;
    int seg = kk0 >> 8;                 // 16-wide slice stays in one segment
    int within = kk0 & 255;
    const float* rsrc = g_rT + (hop - 1 - seg) * NR * NB;
    const float* wd = w + DQ + kk0;
    float a0 = 0.f, a1 = 0.f;
#pragma unroll
    for (int k = 0; k < 16; k += 2) {
        a0 += rsrc[(within + k) * NB + lane] * wd[k];
        a1 += rsrc[(within + k + 1) * NB + lane] * wd[k + 1];
    }
    __shared__ float s[8][32];
    s[ty][lane] = a0 + a1;
    __syncthreads();
    if (ty == 0) {
        float t = 0.f;
#pragma unroll
        for (int k = 0; k < 8; k++) t += s[k][lane];
        if (blockIdx.y == 0)            // add hop-0 base exactly once
            t += (j == 256) ? g_c[lane] : g_rT[j * NB + lane];
        if (j == 256) atomicAdd(&g_c[hop * NB + lane], t);
        else          atomicAdd(&g_rT[hop * NR * NB + j * NB + lane], t);
    }
}

// ---- gather * relation -> vector scatter-add, lane-mask gated at quad
// granularity. Masks are precomputed (reachability), so no mask output. ----
__global__ void k_scatter(const int* __restrict__ subj,
                          const int* __restrict__ rel,
                          const int* __restrict__ obj, int hop) {
    const float* __restrict__ rT = g_rT + hop * NR * NB;
    const float* __restrict__ xin = (hop == 0) ? g_x0T : (g_xh + (hop - 1) * NEB);
    float* xout = g_xh + hop * NEB;
    const unsigned* __restrict__ lmin = g_lm + hop * NE;

    int lane = threadIdx.x & 31;
    int sub = lane >> 3, quad = lane & 7;
    int t = blockIdx.x * blockDim.x + threadIdx.x;

    int s_i = 0, r_i = 0, o_i = 0;
    unsigned lm_i = 0;
    if (t < NT) {
        s_i = subj[t];
        lm_i = lmin[s_i];
        if (lm_i) { r_i = rel[t]; o_i = obj[t]; }
    }
    unsigned bal = __ballot_sync(0xffffffffu, lm_i != 0);
    while (bal) {
        unsigned b = bal;
        int i0 = __ffs(b) - 1; b &= b - 1;
        int i1 = __ffs(b) - 1; b &= b - 1;
        int i2 = __ffs(b) - 1; b &= b - 1;
        int i3 = __ffs(b) - 1; b &= b - 1;
        bal = b;
        int myi = (sub == 0) ? i0 : (sub == 1) ? i1 : (sub == 2) ? i2 : i3;
        bool on = (myi >= 0);
        int src = on ? myi : 0;
        int s = __shfl_sync(0xffffffffu, s_i, src);
        int r = __shfl_sync(0xffffffffu, r_i, src);
        int o = __shfl_sync(0xffffffffu, o_i, src);
        unsigned lmw = __shfl_sync(0xffffffffu, lm_i, src);
        unsigned nib = (lmw >> (quad * 4)) & 0xFu;      // my 4 lanes' activity
        if (on && nib) {
            float4 xv = *reinterpret_cast<const float4*>(&xin[(size_t)s * NB + quad * 4]);
            float4 rv = *reinterpret_cast<const float4*>(&rT[r * NB + quad * 4]);
            float4 p;
            p.x = xv.x * rv.x; p.y = xv.y * rv.y;
            p.z = xv.z * rv.z; p.w = xv.w * rv.w;
            if ((p.x != 0.f) | (p.y != 0.f) | (p.z != 0.f) | (p.w != 0.f)) {
                float* dst = &xout[(size_t)o * NB + quad * 4];
                asm volatile("red.global.add.v4.f32 [%0], {%1,%2,%3,%4};"
                             :: "l"(dst), "f"(p.x), "f"(p.y), "f"(p.z), "f"(p.w)
                             : "memory");
            }
        }
    }
}

// ---- softmax + masked weighted combine, transpose back to (B,NE) ----
__global__ void k_combine(float* __restrict__ out) {
    __shared__ float s[32][33];
    int lane = threadIdx.x, ty = threadIdx.y;
    float c0 = g_c[lane], c1 = g_c[NB + lane], c2 = g_c[2 * NB + lane];
    float m = fmaxf(c0, fmaxf(c1, c2));
    float e0 = expf(c0 - m), e1 = expf(c1 - m), e2 = expf(c2 - m);
    float inv = 1.0f / (e0 + e1 + e2);
    float a0 = e0 * inv, a1 = e1 * inv, a2 = e2 * inv;

    int ebase = blockIdx.x * 32;
#pragma unroll
    for (int row = ty; row < 32; row += 8) {           // row = e offset, lane = b
        int e = ebase + row;
        int idx = e * NB + lane;
        float v = 0.f;
        if (g_lm[NE + e])     v += a0 * g_xh[idx];
        if (g_lm[2 * NE + e]) v += a1 * g_xh[NEB + idx];
        if (g_lm[3 * NE + e]) v += a2 * g_xh[2 * NEB + idx];
        s[row][lane] = v;
    }
    __syncthreads();
#pragma unroll
    for (int row = ty; row < 32; row += 8)             // row = b, lane = e offset
        out[(size_t)row * NE + ebase + lane] = s[lane][row];
}

extern "C" void kernel_launch(void* const* d_in, const int* in_sizes, int n_in,
                              void* d_out, int out_size) {
    const float* x     = (const float*)d_in[0];
    const float* h_q   = (const float*)d_in[1];
    const float* W_inf = (const float*)d_in[2];
    const float* W_att = (const float*)d_in[3];
    const int*   subj  = (const int*)d_in[4];
    const int*   rel   = (const int*)d_in[5];
    const int*   obj   = (const int*)d_in[6];
    float* out = (float*)d_out;

    static cudaStream_t s1 = nullptr, s2 = nullptr;
    static cudaEvent_t eF = nullptr, e1 = nullptr, e2 = nullptr, e3 = nullptr,
                       eB = nullptr, eH1 = nullptr, eH2 = nullptr;
    if (!s1) {
        cudaStreamCreateWithFlags(&s1, cudaStreamNonBlocking);
        cudaStreamCreateWithFlags(&s2, cudaStreamNonBlocking);
        cudaEventCreateWithFlags(&eF,  cudaEventDisableTiming);
        cudaEventCreateWithFlags(&e1,  cudaEventDisableTiming);
        cudaEventCreateWithFlags(&e2,  cudaEventDisableTiming);
        cudaEventCreateWithFlags(&e3,  cudaEventDisableTiming);
        cudaEventCreateWithFlags(&eB,  cudaEventDisableTiming);
        cudaEventCreateWithFlags(&eH1, cudaEventDisableTiming);
        cudaEventCreateWithFlags(&eH2, cudaEventDisableTiming);
    }

    dim3 tb(32, 8);
    const int rblocks = (NT + 255) / 256;
    const int zmblocks = (NE * 8 + 255) / 256;

    // side stream s1: transpose + mask chain + masked zeroing
    cudaEventRecord(eF, 0);
    cudaStreamWaitEvent(s1, eF, 0);
    k_transpose_x<<<NE / 32, tb, 0, s1>>>(x);
    k_zero_lm<<<(3 * NE + 255) / 256, 256, 0, s1>>>();
    k_reach<<<rblocks, 256, 0, s1>>>(subj, obj, 0);
    k_zero_masked<<<zmblocks, 256, 0, s1>>>(0);
    cudaEventRecord(e1, s1);
    k_reach<<<rblocks, 256, 0, s1>>>(subj, obj, 1);
    k_zero_masked<<<zmblocks, 256, 0, s1>>>(1);
    cudaEventRecord(e2, s1);
    k_reach<<<rblocks, 256, 0, s1>>>(subj, obj, 2);
    k_zero_masked<<<zmblocks, 256, 0, s1>>>(2);
    cudaEventRecord(e3, s1);

    // main stream: gemm chain
    k_zero_small<<<(3 * NR * NB + 255) / 256, 256>>>();
    k_gemm_base<<<dim3(NJ, 4), tb>>>(W_inf, W_att, h_q);
    cudaEventRecord(eB, 0);
    cudaStreamWaitEvent(s2, eB, 0);
    k_gemm_hop<<<dim3(NJ, 2), tb, 0, s2>>>(W_inf, W_att, 1);
    cudaEventRecord(eH1, s2);
    k_gemm_hop<<<dim3(NJ, 4), tb, 0, s2>>>(W_inf, W_att, 2);
    cudaEventRecord(eH2, s2);

    int sblocks = (NT + 255) / 256;
    cudaStreamWaitEvent(0, e1, 0);
    k_scatter<<<sblocks, 256>>>(subj, rel, obj, 0);
    cudaStreamWaitEvent(0, eH1, 0);
    cudaStreamWaitEvent(0, e2, 0);
    k_scatter<<<sblocks, 256>>>(subj, rel, obj, 1);
    cudaStreamWaitEvent(0, eH2, 0);
    cudaStreamWaitEvent(0, e3, 0);
    k_scatter<<<sblocks, 256>>>(subj, rel, obj, 2);
    k_combine<<<NE / 32, tb>>>(out);
}

// round 10
// speedup vs baseline: 1.0978x; 1.0978x over previous
#include <cuda_runtime.h>

#define NB   32        // batch
#define NE   200000    // entities
#define NT   1000000   // triples
#define NR   256       // relations
#define DQ   768       // question dim
#define DIN  1280      // DQ + 2*NR
#define NEB  (NE * NB) // 6.4M floats
#define NJ   257       // 256 W_inf rows + 1 W_att row

// ---- device scratch (static; no allocation) ----
__device__ float g_x0T[NEB];           // transposed seed x: [e][b] (active rows)
__device__ float g_xh[3 * NEB];        // hop outputs, entity-major
__device__ float g_rT[3 * NR * NB];    // r per hop: [j][b]
__device__ float g_c[3 * NB];          // attention logits per hop
__device__ unsigned g_lm[4 * NE];      // per-entity 32-bit lane-activity mask per hop

// ---- transpose x (B x NE) -> (NE x B), sparse writes + exact hop-0 lane mask ----
__global__ void k_transpose_x(const float* __restrict__ src) {
    __shared__ float s[32][33];
    int lane = threadIdx.x, ty = threadIdx.y;
    int cbase = blockIdx.x * 32;
#pragma unroll
    for (int row = ty; row < 32; row += 8)              // row = b
        s[row][lane] = src[(size_t)row * NE + cbase + lane];
    __syncthreads();
#pragma unroll
    for (int row = ty; row < 32; row += 8) {            // row = entity offset
        float v = s[lane][row];                         // lane = b
        unsigned b = __ballot_sync(0xffffffffu, v != 0.0f);
        if (b) g_x0T[(size_t)(cbase + row) * NB + lane] = v;  // active rows only
        if (lane == 0) g_lm[cbase + row] = b;           // exact hop-0 lane mask
    }
}

// ---- zero lane masks for hops 1..3 (2.4MB) ----
__global__ void k_zero_lm() {
    int i = blockIdx.x * blockDim.x + threadIdx.x;
    if (i < 3 * NE) g_lm[NE + i] = 0u;
}

// ---- zero one hop output buffer (unconditional, full-bandwidth) ----
__global__ void k_zero_hop(int hop) {
    int i = blockIdx.x * blockDim.x + threadIdx.x;
    if (i < NEB / 4)
        reinterpret_cast<float4*>(g_xh + (size_t)hop * NEB)[i] =
            make_float4(0.f, 0.f, 0.f, 0.f);
}

// ---- zero gemm accumulators ----
__global__ void k_zero_small() {
    int i = blockIdx.x * blockDim.x + threadIdx.x;
    if (i < 3 * NR * NB) g_rT[i] = 0.f;
    if (i < 3 * NB) g_c[i] = 0.f;
}

// ---- r_0 / c_0 = h_q @ [W_inf; W_att][:, :768].T  (split-d, atomic accum)
__global__ void k_gemm_base(const float* __restrict__ W_inf,
                            const float* __restrict__ W_att,
                            const float* __restrict__ h_q) {
    __shared__ float sh[192][33];
    __shared__ float sr[8][32];
    int lane = threadIdx.x, ty = threadIdx.y;
    int tid = ty * 32 + lane;
    int j = blockIdx.x;
    int d0 = blockIdx.y * 192;
#pragma unroll
    for (int k = 0; k < 24; k++) {                      // 6144 elems, coalesced
        int idx = tid + k * 256;
        int b = idx / 192, d = idx % 192;
        sh[d][b] = h_q[(size_t)b * DQ + d0 + d];
    }
    __syncthreads();
    const float* w = (j == 256) ? W_att : W_inf + (size_t)j * DIN;
    int dd = ty * 24;
    float a0 = 0.f, a1 = 0.f, a2 = 0.f, a3 = 0.f;
#pragma unroll
    for (int d = dd; d < dd + 24; d += 4) {
        a0 += sh[d + 0][lane] * w[d0 + d + 0];
        a1 += sh[d + 1][lane] * w[d0 + d + 1];
        a2 += sh[d + 2][lane] * w[d0 + d + 2];
        a3 += sh[d + 3][lane] * w[d0 + d + 3];
    }
    sr[ty][lane] = (a0 + a1) + (a2 + a3);
    __syncthreads();
    if (ty == 0) {
        float t = 0.f;
#pragma unroll
        for (int k = 0; k < 8; k++) t += sr[k][lane];
        if (j == 256) atomicAdd(&g_c[lane], t);
        else          atomicAdd(&g_rT[j * NB + lane], t);
    }
}

// ---- hop 1/2 increment, split-k: out = hop0_out + r_parts @ W[:, 768:].T ----
__global__ void k_gemm_hop(const float* __restrict__ W_inf,
                           const float* __restrict__ W_att, int hop) {
    int lane = threadIdx.x, ty = threadIdx.y;
    int j = blockIdx.x;
    const float* w = (j == 256) ? W_att : W_inf + (size_t)j * DIN;
    int kk0 = blockIdx.y * 128 + ty * 16;
    int seg = kk0 >> 8;                 // 16-wide slice stays in one segment
    int within = kk0 & 255;
    const float* rsrc = g_rT + (hop - 1 - seg) * NR * NB;
    const float* wd = w + DQ + kk0;
    float a0 = 0.f, a1 = 0.f;
#pragma unroll
    for (int k = 0; k < 16; k += 2) {
        a0 += rsrc[(within + k) * NB + lane] * wd[k];
        a1 += rsrc[(within + k + 1) * NB + lane] * wd[k + 1];
    }
    __shared__ float s[8][32];
    s[ty][lane] = a0 + a1;
    __syncthreads();
    if (ty == 0) {
        float t = 0.f;
#pragma unroll
        for (int k = 0; k < 8; k++) t += s[k][lane];
        if (blockIdx.y == 0)            // add hop-0 base exactly once
            t += (j == 256) ? g_c[lane] : g_rT[j * NB + lane];
        if (j == 256) atomicAdd(&g_c[hop * NB + lane], t);
        else          atomicAdd(&g_rT[hop * NR * NB + j * NB + lane], t);
    }
}

// ---- gather * relation -> vector scatter-add.
// Consumes lm[hop] (nibble-gates each quad's gathers) and produces lm[hop+1]
// (3-shuffle sub-reduce of per-lane nonzero bits + one atomicOr per triple). ----
__global__ void k_scatter(const int* __restrict__ subj,
                          const int* __restrict__ rel,
                          const int* __restrict__ obj, int hop) {
    const float* __restrict__ rT = g_rT + hop * NR * NB;
    const float* __restrict__ xin = (hop == 0) ? g_x0T : (g_xh + (hop - 1) * NEB);
    float* xout = g_xh + hop * NEB;
    const unsigned* __restrict__ lmin = g_lm + hop * NE;
    unsigned* lmout = g_lm + (hop + 1) * NE;

    int lane = threadIdx.x & 31;
    int sub = lane >> 3, quad = lane & 7;
    int t = blockIdx.x * blockDim.x + threadIdx.x;

    int s_i = 0, r_i = 0, o_i = 0;
    unsigned lm_i = 0;
    if (t < NT) {
        s_i = subj[t];
        lm_i = lmin[s_i];
        if (lm_i) { r_i = rel[t]; o_i = obj[t]; }
    }
    unsigned bal = __ballot_sync(0xffffffffu, lm_i != 0);
    while (bal) {
        unsigned b = bal;
        int i0 = __ffs(b) - 1; b &= b - 1;
        int i1 = __ffs(b) - 1; b &= b - 1;
        int i2 = __ffs(b) - 1; b &= b - 1;
        int i3 = __ffs(b) - 1; b &= b - 1;
        bal = b;
        int myi = (sub == 0) ? i0 : (sub == 1) ? i1 : (sub == 2) ? i2 : i3;
        bool on = (myi >= 0);
        int src = on ? myi : 0;
        int s = __shfl_sync(0xffffffffu, s_i, src);
        int r = __shfl_sync(0xffffffffu, r_i, src);
        int o = __shfl_sync(0xffffffffu, o_i, src);
        unsigned lmw = __shfl_sync(0xffffffffu, lm_i, src);
        unsigned nib = (lmw >> (quad * 4)) & 0xFu;      // my 4 batch lanes
        unsigned m4 = 0;                                // nonzero bits of my quad
        if (on && nib) {
            float4 xv = *reinterpret_cast<const float4*>(&xin[(size_t)s * NB + quad * 4]);
            float4 rv = *reinterpret_cast<const float4*>(&rT[r * NB + quad * 4]);
            float4 p;
            p.x = xv.x * rv.x; p.y = xv.y * rv.y;
            p.z = xv.z * rv.z; p.w = xv.w * rv.w;
            m4 = (p.x != 0.f) | ((p.y != 0.f) << 1) |
                 ((p.z != 0.f) << 2) | ((p.w != 0.f) << 3);
            if (m4) {
                float* dst = &xout[(size_t)o * NB + quad * 4];
                asm volatile("red.global.add.v4.f32 [%0], {%1,%2,%3,%4};"
                             :: "l"(dst), "f"(p.x), "f"(p.y), "f"(p.z), "f"(p.w)
                             : "memory");
            }
        }
        // or-reduce m4<<(quad*4) across the 8 lanes of this sub (width=8)
        unsigned mm = m4 << (quad * 4);
        mm |= __shfl_down_sync(0xffffffffu, mm, 4, 8);
        mm |= __shfl_down_sync(0xffffffffu, mm, 2, 8);
        mm |= __shfl_down_sync(0xffffffffu, mm, 1, 8);
        if (on && quad == 0 && mm)
            atomicOr(&lmout[o], mm);
    }
}

// ---- softmax + masked weighted combine, transpose back to (B,NE) ----
__global__ void k_combine(float* __restrict__ out) {
    __shared__ float s[32][33];
    int lane = threadIdx.x, ty = threadIdx.y;
    float c0 = g_c[lane], c1 = g_c[NB + lane], c2 = g_c[2 * NB + lane];
    float m = fmaxf(c0, fmaxf(c1, c2));
    float e0 = expf(c0 - m), e1 = expf(c1 - m), e2 = expf(c2 - m);
    float inv = 1.0f / (e0 + e1 + e2);
    float a0 = e0 * inv, a1 = e1 * inv, a2 = e2 * inv;

    int ebase = blockIdx.x * 32;
#pragma unroll
    for (int row = ty; row < 32; row += 8) {           // row = e offset, lane = b
        int e = ebase + row;
        int idx = e * NB + lane;
        float v = 0.f;
        if (g_lm[NE + e])     v += a0 * g_xh[idx];
        if (g_lm[2 * NE + e]) v += a1 * g_xh[NEB + idx];
        if (g_lm[3 * NE + e]) v += a2 * g_xh[2 * NEB + idx];
        s[row][lane] = v;
    }
    __syncthreads();
#pragma unroll
    for (int row = ty; row < 32; row += 8)             // row = b, lane = e offset
        out[(size_t)row * NE + ebase + lane] = s[lane][row];
}

extern "C" void kernel_launch(void* const* d_in, const int* in_sizes, int n_in,
                              void* d_out, int out_size) {
    const float* x     = (const float*)d_in[0];
    const float* h_q   = (const float*)d_in[1];
    const float* W_inf = (const float*)d_in[2];
    const float* W_att = (const float*)d_in[3];
    const int*   subj  = (const int*)d_in[4];
    const int*   rel   = (const int*)d_in[5];
    const int*   obj   = (const int*)d_in[6];
    float* out = (float*)d_out;

    static cudaStream_t s1 = nullptr, s2 = nullptr;
    static cudaEvent_t eF = nullptr, e1 = nullptr, e2 = nullptr, e3 = nullptr,
                       eB = nullptr, eH1 = nullptr, eH2 = nullptr;
    if (!s1) {
        cudaStreamCreateWithFlags(&s1, cudaStreamNonBlocking);
        cudaStreamCreateWithFlags(&s2, cudaStreamNonBlocking);
        cudaEventCreateWithFlags(&eF,  cudaEventDisableTiming);
        cudaEventCreateWithFlags(&e1,  cudaEventDisableTiming);
        cudaEventCreateWithFlags(&e2,  cudaEventDisableTiming);
        cudaEventCreateWithFlags(&e3,  cudaEventDisableTiming);
        cudaEventCreateWithFlags(&eB,  cudaEventDisableTiming);
        cudaEventCreateWithFlags(&eH1, cudaEventDisableTiming);
        cudaEventCreateWithFlags(&eH2, cudaEventDisableTiming);
    }

    dim3 tb(32, 8);
    const int zblocks = (NEB / 4 + 255) / 256;

    // side stream s1: lm zero + transpose + zero hop0, then zero hop2
    cudaEventRecord(eF, 0);
    cudaStreamWaitEvent(s1, eF, 0);
    k_zero_lm<<<(3 * NE + 255) / 256, 256, 0, s1>>>();
    k_transpose_x<<<NE / 32, tb, 0, s1>>>(x);
    k_zero_hop<<<zblocks, 256, 0, s1>>>(0);
    cudaEventRecord(e1, s1);
    k_zero_hop<<<zblocks, 256, 0, s1>>>(2);
    cudaEventRecord(e3, s1);

    // main stream: gemm chain
    k_zero_small<<<(3 * NR * NB + 255) / 256, 256>>>();
    k_gemm_base<<<dim3(NJ, 4), tb>>>(W_inf, W_att, h_q);
    cudaEventRecord(eB, 0);
    // s2: gemm hops, then zero hop1
    cudaStreamWaitEvent(s2, eB, 0);
    k_gemm_hop<<<dim3(NJ, 2), tb, 0, s2>>>(W_inf, W_att, 1);
    cudaEventRecord(eH1, s2);
    k_gemm_hop<<<dim3(NJ, 4), tb, 0, s2>>>(W_inf, W_att, 2);
    cudaEventRecord(eH2, s2);
    k_zero_hop<<<zblocks, 256, 0, s2>>>(1);
    cudaEventRecord(e2, s2);

    int sblocks = (NT + 255) / 256;
    cudaStreamWaitEvent(0, e1, 0);
    k_scatter<<<sblocks, 256>>>(subj, rel, obj, 0);
    cudaStreamWaitEvent(0, e2, 0);      // covers eH1 (same stream, earlier)
    k_scatter<<<sblocks, 256>>>(subj, rel, obj, 1);
    cudaStreamWaitEvent(0, eH2, 0);
    cudaStreamWaitEvent(0, e3, 0);
    k_scatter<<<sblocks, 256>>>(subj, rel, obj, 2);
    k_combine<<<NE / 32, tb>>>(out);
}

// round 12
// speedup vs baseline: 1.1900x; 1.0839x over previous
#include <cuda_runtime.h>

#define NB   32        // batch
#define NE   200000    // entities
#define NT   1000000   // triples
#define NR   256       // relations
#define DQ   768       // question dim
#define DIN  1280      // DQ + 2*NR
#define NEB  (NE * NB) // 6.4M floats
#define NJ   257       // 256 W_inf rows + 1 W_att row

// ---- device scratch (static; no allocation) ----
__device__ float g_x0T[NEB];           // transposed seed x: [e][b] (active rows)
__device__ float g_xh[3 * NEB];        // hop outputs, entity-major
__device__ float g_rT[3 * NR * NB];    // r per hop: [j][b]
__device__ float g_c[3 * NB];          // attention logits per hop
__device__ unsigned g_lm[4 * NE];      // per-entity 32-bit lane-activity mask per hop

// ======= kernel 0: zero gemm accumulators (must precede phase1's atomics) ===
__global__ void k_zero_acc() {
    int i = blockIdx.x * blockDim.x + threadIdx.x;
    if (i < 3 * NR * NB) g_rT[i] = 0.f;
    if (i < 3 * NB) g_c[i] = 0.f;
}

// ================= phase 1: transpose + big zeroing + gemm_base =============
// Block ranges (256 threads each):
//   [0, B_GB)              gemm_base  (j = b/4, d-chunk = b%4)
//   [B_GB, +B_TX)          transpose_x
//   [.., +B_ZX)            zero g_xh (1024 float4 per block)
//   [.., +B_ZM)            zero g_lm[NE..4NE)
#define B_GB (NJ * 4)                          // 1028
#define B_TX (NE / 32)                         // 6250
#define B_ZX ((3 * NEB / 4 + 1023) / 1024)     // 4688
#define B_ZM ((3 * NE + 255) / 256)            // 2344
#define B_P1 (B_GB + B_TX + B_ZX + B_ZM)

__global__ void k_phase1(const float* __restrict__ x,
                         const float* __restrict__ h_q,
                         const float* __restrict__ W_inf,
                         const float* __restrict__ W_att) {
    int bid = blockIdx.x;
    int tid = threadIdx.x;
    int lane = tid & 31, ty = tid >> 5;

    if (bid < B_GB) {
        // ---- gemm_base: r_0/c_0 = h_q @ [W_inf; W_att][:, :768].T ----
        __shared__ float sh[192][33];
        __shared__ float sr[8][32];
        int j = bid >> 2;
        int d0 = (bid & 3) * 192;
#pragma unroll
        for (int k = 0; k < 24; k++) {                  // 6144 elems, coalesced
            int idx = tid + k * 256;
            int b = idx / 192, d = idx % 192;
            sh[d][b] = h_q[(size_t)b * DQ + d0 + d];
        }
        __syncthreads();
        const float* w = (j == 256) ? W_att : W_inf + (size_t)j * DIN;
        int dd = ty * 24;
        float a0 = 0.f, a1 = 0.f, a2 = 0.f, a3 = 0.f;
#pragma unroll
        for (int d = dd; d < dd + 24; d += 4) {
            a0 += sh[d + 0][lane] * w[d0 + d + 0];
            a1 += sh[d + 1][lane] * w[d0 + d + 1];
            a2 += sh[d + 2][lane] * w[d0 + d + 2];
            a3 += sh[d + 3][lane] * w[d0 + d + 3];
        }
        sr[ty][lane] = (a0 + a1) + (a2 + a3);
        __syncthreads();
        if (ty == 0) {
            float t = 0.f;
#pragma unroll
            for (int k = 0; k < 8; k++) t += sr[k][lane];
            if (j == 256) atomicAdd(&g_c[lane], t);
            else          atomicAdd(&g_rT[j * NB + lane], t);
        }
    } else if (bid < B_GB + B_TX) {
        // ---- transpose x (B x NE) -> (NE x B), sparse writes + hop-0 lane mask
        __shared__ float s[32][33];
        int cbase = (bid - B_GB) * 32;
#pragma unroll
        for (int row = ty; row < 32; row += 8)          // row = b
            s[row][lane] = x[(size_t)row * NE + cbase + lane];
        __syncthreads();
#pragma unroll
        for (int row = ty; row < 32; row += 8) {        // row = entity offset
            float v = s[lane][row];                     // lane = b
            unsigned b = __ballot_sync(0xffffffffu, v != 0.0f);
            if (b) g_x0T[(size_t)(cbase + row) * NB + lane] = v;
            if (lane == 0) g_lm[cbase + row] = b;       // exact hop-0 lane mask
        }
    } else if (bid < B_GB + B_TX + B_ZX) {
        // ---- zero g_xh (4 float4 per thread) ----
        int base = (bid - B_GB - B_TX) * 1024 + tid;
        const int nq = 3 * NEB / 4;
#pragma unroll
        for (int k = 0; k < 4; k++) {
            int i = base + k * 256;
            if (i < nq)
                reinterpret_cast<float4*>(g_xh)[i] = make_float4(0.f, 0.f, 0.f, 0.f);
        }
    } else {
        // ---- zero lm[1..3] ----
        int i = (bid - B_GB - B_TX - B_ZX) * 256 + tid;
        if (i < 3 * NE) g_lm[NE + i] = 0u;
    }
}

// ================= shared device pieces for phases 2-4 ======================
// hop gemm increment: out_hop = hop0_out + r_parts @ W[:, 768:768+hop*256].T
__device__ __forceinline__ void gemm_hop_body(const float* __restrict__ W_inf,
                                              const float* __restrict__ W_att,
                                              int hop, int j, int yb,
                                              int lane, int ty) {
    __shared__ float s[8][32];
    const float* w = (j == 256) ? W_att : W_inf + (size_t)j * DIN;
    int kk0 = yb * 128 + ty * 16;
    int seg = kk0 >> 8;
    int within = kk0 & 255;
    const float* rsrc = g_rT + (hop - 1 - seg) * NR * NB;
    const float* wd = w + DQ + kk0;
    float a0 = 0.f, a1 = 0.f;
#pragma unroll
    for (int k = 0; k < 16; k += 2) {
        a0 += rsrc[(within + k) * NB + lane] * wd[k];
        a1 += rsrc[(within + k + 1) * NB + lane] * wd[k + 1];
    }
    s[ty][lane] = a0 + a1;
    __syncthreads();
    if (ty == 0) {
        float t = 0.f;
#pragma unroll
        for (int k = 0; k < 8; k++) t += s[k][lane];
        if (yb == 0)
            t += (j == 256) ? g_c[lane] : g_rT[j * NB + lane];
        if (j == 256) atomicAdd(&g_c[hop * NB + lane], t);
        else          atomicAdd(&g_rT[hop * NR * NB + j * NB + lane], t);
    }
}

// scatter: lane-mask-gated gather*relation -> red.v4 scatter; produces lm[hop+1]
__device__ __forceinline__ void scatter_body(const int* __restrict__ subj,
                                             const int* __restrict__ rel,
                                             const int* __restrict__ obj,
                                             int hop, int sblk, int tid) {
    const float* __restrict__ rT = g_rT + hop * NR * NB;
    const float* __restrict__ xin = (hop == 0) ? g_x0T : (g_xh + (hop - 1) * NEB);
    float* xout = g_xh + hop * NEB;
    const unsigned* __restrict__ lmin = g_lm + hop * NE;
    unsigned* lmout = g_lm + (hop + 1) * NE;

    int lane = tid & 31;
    int sub = lane >> 3, quad = lane & 7;
    int t = sblk * 256 + tid;

    int s_i = 0, r_i = 0, o_i = 0;
    unsigned lm_i = 0;
    if (t < NT) {
        s_i = subj[t];
        lm_i = lmin[s_i];
        if (lm_i) { r_i = rel[t]; o_i = obj[t]; }
    }
    unsigned bal = __ballot_sync(0xffffffffu, lm_i != 0);
    while (bal) {
        unsigned b = bal;
        int i0 = __ffs(b) - 1; b &= b - 1;
        int i1 = __ffs(b) - 1; b &= b - 1;
        int i2 = __ffs(b) - 1; b &= b - 1;
        int i3 = __ffs(b) - 1; b &= b - 1;
        bal = b;
        int myi = (sub == 0) ? i0 : (sub == 1) ? i1 : (sub == 2) ? i2 : i3;
        bool on = (myi >= 0);
        int src = on ? myi : 0;
        int s = __shfl_sync(0xffffffffu, s_i, src);
        int r = __shfl_sync(0xffffffffu, r_i, src);
        int o = __shfl_sync(0xffffffffu, o_i, src);
        unsigned lmw = __shfl_sync(0xffffffffu, lm_i, src);
        unsigned nib = (lmw >> (quad * 4)) & 0xFu;
        unsigned m4 = 0;
        if (on && nib) {
            float4 xv = *reinterpret_cast<const float4*>(&xin[(size_t)s * NB + quad * 4]);
            float4 rv = *reinterpret_cast<const float4*>(&rT[r * NB + quad * 4]);
            float4 p;
            p.x = xv.x * rv.x; p.y = xv.y * rv.y;
            p.z = xv.z * rv.z; p.w = xv.w * rv.w;
            m4 = (p.x != 0.f) | ((p.y != 0.f) << 1) |
                 ((p.z != 0.f) << 2) | ((p.w != 0.f) << 3);
            if (m4) {
                float* dst = &xout[(size_t)o * NB + quad * 4];
                asm volatile("red.global.add.v4.f32 [%0], {%1,%2,%3,%4};"
                             :: "l"(dst), "f"(p.x), "f"(p.y), "f"(p.z), "f"(p.w)
                             : "memory");
            }
        }
        unsigned mm = m4 << (quad * 4);
        mm |= __shfl_down_sync(0xffffffffu, mm, 4, 8);
        mm |= __shfl_down_sync(0xffffffffu, mm, 2, 8);
        mm |= __shfl_down_sync(0xffffffffu, mm, 1, 8);
        if (on && quad == 0 && mm)
            atomicOr(&lmout[o], mm);
    }
}

#define B_SC ((NT + 255) / 256)   // 3907 scatter blocks

// ============ phase 2: gemm_hop1 (NJ*2 blocks) + scatter hop0 ===============
__global__ void k_phase2(const int* __restrict__ subj, const int* __restrict__ rel,
                         const int* __restrict__ obj,
                         const float* __restrict__ W_inf,
                         const float* __restrict__ W_att) {
    int bid = blockIdx.x, tid = threadIdx.x;
    if (bid < NJ * 2)
        gemm_hop_body(W_inf, W_att, 1, bid >> 1, bid & 1, tid & 31, tid >> 5);
    else
        scatter_body(subj, rel, obj, 0, bid - NJ * 2, tid);
}

// ============ phase 3: gemm_hop2 (NJ*4 blocks) + scatter hop1 ===============
__global__ void k_phase3(const int* __restrict__ subj, const int* __restrict__ rel,
                         const int* __restrict__ obj,
                         const float* __restrict__ W_inf,
                         const float* __restrict__ W_att) {
    int bid = blockIdx.x, tid = threadIdx.x;
    if (bid < NJ * 4)
        gemm_hop_body(W_inf, W_att, 2, bid >> 2, bid & 3, tid & 31, tid >> 5);
    else
        scatter_body(subj, rel, obj, 1, bid - NJ * 4, tid);
}

// ============ phase 4: scatter hop2 =========================================
__global__ void k_phase4(const int* __restrict__ subj, const int* __restrict__ rel,
                         const int* __restrict__ obj) {
    scatter_body(subj, rel, obj, 2, blockIdx.x, threadIdx.x);
}

// ============ phase 5: softmax + masked combine + transpose out =============
__global__ void k_combine(float* __restrict__ out) {
    __shared__ float s[32][33];
    int lane = threadIdx.x & 31, ty = threadIdx.x >> 5;
    float c0 = g_c[lane], c1 = g_c[NB + lane], c2 = g_c[2 * NB + lane];
    float m = fmaxf(c0, fmaxf(c1, c2));
    float e0 = expf(c0 - m), e1 = expf(c1 - m), e2 = expf(c2 - m);
    float inv = 1.0f / (e0 + e1 + e2);
    float a0 = e0 * inv, a1 = e1 * inv, a2 = e2 * inv;

    int ebase = blockIdx.x * 32;
#pragma unroll
    for (int row = ty; row < 32; row += 8) {           // row = e offset, lane = b
        int e = ebase + row;
        int idx = e * NB + lane;
        float v = 0.f;
        if (g_lm[NE + e])     v += a0 * g_xh[idx];
        if (g_lm[2 * NE + e]) v += a1 * g_xh[NEB + idx];
        if (g_lm[3 * NE + e]) v += a2 * g_xh[2 * NEB + idx];
        s[row][lane] = v;
    }
    __syncthreads();
#pragma unroll
    for (int row = ty; row < 32; row += 8)             // row = b, lane = e offset
        out[(size_t)row * NE + ebase + lane] = s[lane][row];
}

extern "C" void kernel_launch(void* const* d_in, const int* in_sizes, int n_in,
                              void* d_out, int out_size) {
    const float* x     = (const float*)d_in[0];
    const float* h_q   = (const float*)d_in[1];
    const float* W_inf = (const float*)d_in[2];
    const float* W_att = (const float*)d_in[3];
    const int*   subj  = (const int*)d_in[4];
    const int*   rel   = (const int*)d_in[5];
    const int*   obj   = (const int*)d_in[6];
    float* out = (float*)d_out;

    k_zero_acc<<<(3 * NR * NB + 255) / 256, 256>>>();
    k_phase1<<<B_P1, 256>>>(x, h_q, W_inf, W_att);
    k_phase2<<<NJ * 2 + B_SC, 256>>>(subj, rel, obj, W_inf, W_att);
    k_phase3<<<NJ * 4 + B_SC, 256>>>(subj, rel, obj, W_inf, W_att);
    k_phase4<<<B_SC, 256>>>(subj, rel, obj);
    k_combine<<<NE / 32, 256>>>(out);
}